// round 1
// baseline (speedup 1.0000x reference)
#include <cuda_runtime.h>
#include <math.h>

#define BB 4
#define DD 64
#define NV (DD*DD*DD)        // 262144 voxels per batch (2^18)
#define TOT (BB*NV)          // 1048576
#define NP 512               // points per batch

// -------- scratch (device globals: no allocations allowed) --------
__device__ double g_part[256];
__device__ float  g_mean;
__device__ int    g_parent[TOT];   // -1 = background, else union-find parent
__device__ int    g_num[BB];       // component count per batch
__device__ int    g_hit[BB*NP];    // label hit per point (0 = background)

// -------- 1) deterministic mean: two fixed-order tree reductions ----------
__global__ void k_reduce1(const float* __restrict__ x) {
    __shared__ double sh[256];
    const int t = threadIdx.x, bk = blockIdx.x;
    const int CH = TOT / 256;              // 4096 per block
    const int base = bk * CH;
    double s = 0.0;
    for (int i = t; i < CH; i += 256) s += (double)x[base + i];
    sh[t] = s; __syncthreads();
    for (int o = 128; o > 0; o >>= 1) { if (t < o) sh[t] += sh[t + o]; __syncthreads(); }
    if (t == 0) g_part[bk] = sh[0];
}

__global__ void k_reduce2() {
    __shared__ double sh[256];
    const int t = threadIdx.x;
    sh[t] = g_part[t]; __syncthreads();
    for (int o = 128; o > 0; o >>= 1) { if (t < o) sh[t] += sh[t + o]; __syncthreads(); }
    if (t == 0) g_mean = (float)(sh[0] / (double)TOT);
    if (t < BB) g_num[t] = 0;              // re-zero every replay
}

// -------- 2) init labels ----------
__global__ void k_init(const float* __restrict__ x) {
    const int i = blockIdx.x * blockDim.x + threadIdx.x;
    if (i >= TOT) return;
    g_parent[i] = (x[i] > g_mean) ? i : -1;
}

// -------- union-find primitives (lock-free, atomicMin link-at-root) ----------
__device__ __forceinline__ int uf_find(int i) {
    int p = g_parent[i];
    while (p != i) { i = p; p = g_parent[i]; }
    return i;
}

__device__ __forceinline__ void uf_unite(int a, int b) {
    while (true) {
        a = uf_find(a);
        b = uf_find(b);
        if (a == b) return;
        if (a > b) { int t = a; a = b; b = t; }
        int old = atomicMin(&g_parent[b], a);   // only succeeds if b still a root
        if (old == b) return;
        b = old;                                 // someone re-parented b; retry
    }
}

// -------- 3) merge: 3 negative-direction edges per voxel ----------
__global__ void k_merge() {
    const int i = blockIdx.x * blockDim.x + threadIdx.x;
    if (i >= TOT) return;
    if (g_parent[i] < 0) return;
    const int local = i & (NV - 1);
    const int x = local & 63;
    const int y = (local >> 6) & 63;
    const int z = local >> 12;
    if (x > 0 && g_parent[i - 1]    >= 0) uf_unite(i, i - 1);
    if (y > 0 && g_parent[i - 64]   >= 0) uf_unite(i, i - 64);
    if (z > 0 && g_parent[i - 4096] >= 0) uf_unite(i, i - 4096);
}

// -------- 4) flatten to roots ----------
__global__ void k_flatten() {
    const int i = blockIdx.x * blockDim.x + threadIdx.x;
    if (i >= TOT) return;
    if (g_parent[i] < 0) return;
    g_parent[i] = uf_find(i);
}

// -------- 5) count component roots per batch ----------
__global__ void k_count() {
    const int i = blockIdx.x * blockDim.x + threadIdx.x;
    if (i >= TOT) return;
    if (g_parent[i] == i) atomicAdd(&g_num[i >> 18], 1);
}

// -------- 6) point -> label lookup ----------
__global__ void k_lookup(const float* __restrict__ pts) {
    const int t = blockIdx.x * blockDim.x + threadIdx.x;
    if (t >= BB * NP) return;
    const float* p = pts + t * 3;
    const int s0 = (int)p[0];              // pts in [0, 64-1e-3): trunc == floor
    const int s1 = (int)p[1];
    const int s2 = (int)p[2];
    const int b = t / NP;
    const int flat = (b << 18) + (s0 << 12) + (s1 << 6) + s2;
    const int pr = g_parent[flat];
    g_hit[t] = (pr >= 0) ? (pr + 1) : 0;
}

// -------- 7) per-batch RMS over hit histogram (O(P^2) in shared) ----------
__global__ void k_rms(float* __restrict__ out) {
    __shared__ int sh[NP];
    __shared__ int s_h0, s_sq, s_nc;
    const int b = blockIdx.x, t = threadIdx.x;
    sh[t] = g_hit[b * NP + t];
    if (t == 0) { s_h0 = 0; s_sq = 0; s_nc = 0; }
    __syncthreads();
    const int h = sh[t];
    int cnt = 0, first = -1;
    #pragma unroll 8
    for (int j = 0; j < NP; j++) {
        if (sh[j] == h) { if (cnt == 0) first = j; cnt++; }
    }
    if (h == 0) {
        atomicAdd(&s_h0, 1);
    } else if (first == t) {               // representative of a hit component
        const int d = cnt - 1;
        atomicAdd(&s_sq, d * d);           // (1-cnt)^2, exact in int
        atomicAdd(&s_nc, 1);
    }
    __syncthreads();
    if (t == 0) {
        const float num = (float)g_num[b];
        const float sq = (float)s_h0 * (float)s_h0
                       + (float)s_sq
                       + (num - (float)s_nc);   // unhit components
        out[b] = sqrtf(sq / (num + 1.0f));
    }
}

// -------- launcher ----------
extern "C" void kernel_launch(void* const* d_in, const int* in_sizes, int n_in,
                              void* d_out, int out_size) {
    const float* logits = (const float*)d_in[0];
    const float* pts    = (const float*)d_in[1];
    if (n_in >= 2 && in_sizes[0] != TOT) {   // defensive input-order check
        logits = (const float*)d_in[1];
        pts    = (const float*)d_in[0];
    }
    k_reduce1<<<256, 256>>>(logits);
    k_reduce2<<<1, 256>>>();
    k_init<<<TOT / 256, 256>>>(logits);
    k_merge<<<TOT / 256, 256>>>();
    k_flatten<<<TOT / 256, 256>>>();
    k_count<<<TOT / 256, 256>>>();
    k_lookup<<<(BB * NP + 255) / 256, 256>>>(pts);
    k_rms<<<BB, NP>>>((float*)d_out);
}